// round 8
// baseline (speedup 1.0000x reference)
#include <cuda_runtime.h>
#include <cstdint>
#include <math.h>

#define T_TOK 1024
#define H_DIM 1024
#define N_EXP 8
#define I_DIM 1024
#define ALPHA 1.702f
#define LIMIT 7.0f

// ---------------- device scratch (no allocations allowed) --------------------
__device__ int      g_cnt[N_EXP];
__device__ int      g_tok[N_EXP * T_TOK];
__device__ float    g_wt [N_EXP * T_TOK];
// fp16 operand planes, packed 2 elems per u32
__device__ __align__(16) uint32_t g_x_f16  [(size_t)T_TOK * H_DIM / 2];
__device__ __align__(16) uint32_t g_gup_f16[(size_t)N_EXP * H_DIM * 2 * I_DIM / 2];
__device__ __align__(16) uint32_t g_dwn_f16[(size_t)N_EXP * I_DIM * H_DIM / 2];
__device__ __align__(16) uint32_t g_act_f16[(size_t)N_EXP * T_TOK * I_DIM / 2];

// ---------------- helpers ----------------------------------------------------
__device__ __forceinline__ uint32_t smem_u32(const void* p) {
    uint32_t a;
    asm("{ .reg .u64 t; cvta.to.shared.u64 t, %1; cvt.u32.u64 %0, t; }"
        : "=r"(a) : "l"(p));
    return a;
}
__device__ __forceinline__ uint32_t swz128(uint32_t off) { return off ^ ((off >> 3) & 0x70); }

__device__ __forceinline__ uint32_t pack_f16x2(float a, float b) {
    uint32_t r;
    asm("cvt.rn.f16x2.f32 %0, %1, %2;" : "=r"(r) : "f"(b), "f"(a));  // a -> low half
    return r;
}

__device__ __forceinline__ void ldsm4(uint32_t* r, uint32_t a) {
    asm volatile("ldmatrix.sync.aligned.m8n8.x4.shared.b16 {%0,%1,%2,%3}, [%4];"
        : "=r"(r[0]), "=r"(r[1]), "=r"(r[2]), "=r"(r[3]) : "r"(a));
}
__device__ __forceinline__ void ldsm4t(uint32_t* r, uint32_t a) {
    asm volatile("ldmatrix.sync.aligned.m8n8.x4.trans.shared.b16 {%0,%1,%2,%3}, [%4];"
        : "=r"(r[0]), "=r"(r[1]), "=r"(r[2]), "=r"(r[3]) : "r"(a));
}
__device__ __forceinline__ void mma16816(float* c, const uint32_t* a, uint32_t b0, uint32_t b1) {
    asm volatile("mma.sync.aligned.m16n8k16.row.col.f32.f16.f16.f32 "
        "{%0,%1,%2,%3}, {%4,%5,%6,%7}, {%8,%9}, {%0,%1,%2,%3};"
        : "+f"(c[0]), "+f"(c[1]), "+f"(c[2]), "+f"(c[3])
        : "r"(a[0]), "r"(a[1]), "r"(a[2]), "r"(a[3]), "r"(b0), "r"(b1));
}

#define CP16(dst, src) \
    asm volatile("cp.async.cg.shared.global [%0], [%1], 16;" :: "r"(dst), "l"(src) : "memory")
#define CP_COMMIT() asm volatile("cp.async.commit_group;" ::: "memory")
#define CP_WAIT1()  asm volatile("cp.async.wait_group 1;" ::: "memory")

// ---------------- kernel: fp32 -> packed fp16 (32B/thread) -------------------
__global__ void convert_kernel(const float4* __restrict__ src,
                               uint2* __restrict__ dst, int n4) {
    int i = (blockIdx.x * blockDim.x + threadIdx.x) * 2;
    if (i >= n4) return;
    float4 v0 = src[i];
    float4 v1 = src[i + 1];
    dst[i]     = make_uint2(pack_f16x2(v0.x, v0.y), pack_f16x2(v0.z, v0.w));
    dst[i + 1] = make_uint2(pack_f16x2(v1.x, v1.y), pack_f16x2(v1.z, v1.w));
}

// ---------------- kernel 0: zero ---------------------------------------------
__global__ void zero_kernel(float4* __restrict__ out) {
    int i = blockIdx.x * blockDim.x + threadIdx.x;
    if (i < T_TOK * H_DIM / 4) out[i] = make_float4(0.f, 0.f, 0.f, 0.f);
    if (i < N_EXP) g_cnt[i] = 0;
}

// ---------------- kernel 1: router -------------------------------------------
__global__ void router_kernel(const float* __restrict__ x,
                              const float* __restrict__ rw,
                              const float* __restrict__ rb) {
    const int t = blockIdx.x;
    __shared__ float s[N_EXP][128];
    float p[N_EXP];
#pragma unroll
    for (int e = 0; e < N_EXP; e++) p[e] = 0.0f;
    const float* xr = x + (size_t)t * H_DIM;
    for (int h = threadIdx.x; h < H_DIM; h += 128) {
        float xv = xr[h];
#pragma unroll
        for (int e = 0; e < N_EXP; e++) p[e] += xv * rw[e * H_DIM + h];
    }
#pragma unroll
    for (int e = 0; e < N_EXP; e++) s[e][threadIdx.x] = p[e];
    __syncthreads();
    if (threadIdx.x == 0) {
        float l[N_EXP], mx = -1e30f;
#pragma unroll
        for (int e = 0; e < N_EXP; e++) {
            float sum = 0.0f;
            for (int i = 0; i < 128; i++) sum += s[e][i];
            l[e] = sum + rb[e];
            mx = fmaxf(mx, l[e]);
        }
        float den = 0.0f, sc[N_EXP];
#pragma unroll
        for (int e = 0; e < N_EXP; e++) { sc[e] = expf(l[e] - mx); den += sc[e]; }
        float inv = 1.0f / den;
#pragma unroll
        for (int e = 0; e < N_EXP; e++) sc[e] *= inv;
        int i0 = 0;
#pragma unroll
        for (int e = 1; e < N_EXP; e++) if (sc[e] > sc[i0]) i0 = e;
        int i1 = (i0 == 0) ? 1 : 0;
#pragma unroll
        for (int e = 0; e < N_EXP; e++) if (e != i0 && sc[e] > sc[i1]) i1 = e;
        int p0 = atomicAdd(&g_cnt[i0], 1);
        g_tok[i0 * T_TOK + p0] = t; g_wt[i0 * T_TOK + p0] = sc[i0];
        int p1 = atomicAdd(&g_cnt[i1], 1);
        g_tok[i1 * T_TOK + p1] = t; g_wt[i1 * T_TOK + p1] = sc[i1];
    }
}

// ---------------- kernel 2: gate_up HMMA (fp16, BK=64, 3-stage) --------------
// Stage (32KB): A 16KB (128 rows x 128B, SW128), BG 8KB, BU 8KB (64 k-rows x 128B)
#define GU_A      0
#define GU_BG     16384
#define GU_BU     24576
#define GU_STRIDE 32768
#define STAGES    3
#define N_ITERS   16

__global__ __launch_bounds__(256, 2)
void moe_gateup_hmma(const float* __restrict__ gub) {
    const int e   = blockIdx.z;
    const int cnt = g_cnt[e];
    const int m0  = blockIdx.x * 128;
    if (m0 >= cnt) return;
    const int n0  = blockIdx.y * 64;

    extern __shared__ char dsm[];
    __shared__ int s_tok[128];
    const uint32_t dbase = (smem_u32(dsm) + 1023u) & ~1023u;

    const int tid = threadIdx.x, lane = tid & 31, wid = tid >> 5;
    const int mw = wid >> 1, nw = wid & 1;

    if (tid < 128) {
        int gm = m0 + tid;
        s_tok[tid] = (gm < cnt) ? g_tok[e * T_TOK + gm] : g_tok[e * T_TOK];
    }
    __syncthreads();

    // A loader: row rA (0..127), 64B half hA (4 x 16B chunks)
    const int rA = tid >> 1, hA = tid & 1;
    const int tA = s_tok[rA];
    // B loader: k-row kB (0..63), 16B chunks pB and pB+4 (per matrix)
    const int kB = tid >> 2, pB = tid & 3;
    const size_t gupb = (size_t)e * (H_DIM * I_DIM);      // u32; row stride 1024

#define GU_ISSUE(s_) do { if ((s_) < N_ITERS) {                                              \
    uint32_t bb = dbase + ((s_) % STAGES) * GU_STRIDE;                                       \
    const uint32_t* ga = g_x_f16 + (size_t)tA * 512 + (s_) * 32 + hA * 16;                   \
    _Pragma("unroll") for (int q = 0; q < 4; q++)                                            \
        CP16(bb + GU_A + swz128(rA * 128 + hA * 64 + q * 16), ga + q * 4);                   \
    size_t bro = gupb + (size_t)((s_) * 64 + kB) * 1024 + (n0 >> 1);                         \
    _Pragma("unroll") for (int h = 0; h < 2; h++) {                                          \
        CP16(bb + GU_BG + swz128(kB * 128 + (pB + h * 4) * 16), g_gup_f16 + bro + (pB + h * 4) * 4);        \
        CP16(bb + GU_BU + swz128(kB * 128 + (pB + h * 4) * 16), g_gup_f16 + bro + 512 + (pB + h * 4) * 4);  \
    }                                                                                        \
} CP_COMMIT(); } while (0)

    float cg[2][4][4], cu[2][4][4];
#pragma unroll
    for (int a = 0; a < 2; a++)
#pragma unroll
        for (int b = 0; b < 4; b++)
#pragma unroll
            for (int c = 0; c < 4; c++) { cg[a][b][c] = 0.f; cu[a][b][c] = 0.f; }

    GU_ISSUE(0);
    GU_ISSUE(1);

#pragma unroll 1
    for (int it = 0; it < N_ITERS; ++it) {
        CP_WAIT1();
        __syncthreads();
        GU_ISSUE(it + 2);
        uint32_t base = dbase + (it % STAGES) * GU_STRIDE;
#pragma unroll
        for (int s = 0; s < 4; s++) {
            uint32_t am[2][4];
#pragma unroll
            for (int mt = 0; mt < 2; mt++) {
                uint32_t row = mw * 32 + mt * 16 + (lane & 15);
                uint32_t co  = s * 32 + ((lane >> 4) << 4);
                ldsm4(am[mt], base + GU_A + swz128(row * 128 + co));
            }
            uint32_t krow = s * 16 + (lane & 15);
            uint32_t ccol = nw * 64 + ((lane >> 4) << 4);
            uint32_t bg[8], bu[8];
#pragma unroll
            for (int h = 0; h < 2; h++) {
                ldsm4t(bg + 4 * h, base + GU_BG + swz128(krow * 128 + ccol + h * 32));
                ldsm4t(bu + 4 * h, base + GU_BU + swz128(krow * 128 + ccol + h * 32));
            }
#pragma unroll
            for (int mt = 0; mt < 2; mt++)
#pragma unroll
                for (int nf = 0; nf < 4; nf++) {
                    mma16816(cg[mt][nf], am[mt], bg[2*nf], bg[2*nf+1]);
                    mma16816(cu[mt][nf], am[mt], bu[2*nf], bu[2*nf+1]);
                }
        }
    }
#undef GU_ISSUE

    // epilogue: bias + clamped GLU -> g_act (packed fp16)
    const float* gb = gub + e * 2 * I_DIM;
#pragma unroll
    for (int mt = 0; mt < 2; mt++)
#pragma unroll
        for (int r = 0; r < 2; r++) {
            int slot = m0 + mw * 32 + mt * 16 + (lane >> 2) + r * 8;
            if (slot >= cnt) continue;
            size_t abase = ((size_t)(e * T_TOK + slot) * I_DIM) >> 1;
#pragma unroll
            for (int nf = 0; nf < 4; nf++) {
                int col = n0 + nw * 32 + nf * 8 + (lane & 3) * 2;
                float g0 = cg[mt][nf][2 * r]     + gb[col];
                float g1 = cg[mt][nf][2 * r + 1] + gb[col + 1];
                float u0 = cu[mt][nf][2 * r]     + gb[I_DIM + col];
                float u1 = cu[mt][nf][2 * r + 1] + gb[I_DIM + col + 1];
                g0 = fminf(g0, LIMIT); g1 = fminf(g1, LIMIT);
                u0 = fminf(fmaxf(u0, -LIMIT), LIMIT);
                u1 = fminf(fmaxf(u1, -LIMIT), LIMIT);
                float a0 = (u0 + 1.0f) * (g0 / (1.0f + __expf(-ALPHA * g0)));
                float a1 = (u1 + 1.0f) * (g1 / (1.0f + __expf(-ALPHA * g1)));
                g_act_f16[abase + (col >> 1)] = pack_f16x2(a0, a1);
            }
        }
}

// ---------------- kernel 3: down HMMA (fp16, BK=64, 3-stage) -----------------
// Stage (24KB): A 16KB (SW128, 128B rows), B 8KB
#define DN_A      0
#define DN_B      16384
#define DN_STRIDE 24576

__global__ __launch_bounds__(256, 2)
void moe_down_hmma(const float* __restrict__ dnb, float* __restrict__ out) {
    const int e   = blockIdx.z;
    const int cnt = g_cnt[e];
    const int m0  = blockIdx.x * 128;
    if (m0 >= cnt) return;
    const int n0  = blockIdx.y * 64;

    extern __shared__ char dsm[];
    const uint32_t dbase = (smem_u32(dsm) + 1023u) & ~1023u;

    const int tid = threadIdx.x, lane = tid & 31, wid = tid >> 5;
    const int mw = wid >> 1, nw = wid & 1;

    const int rA = tid >> 1, hA = tid & 1;
    const int kB = tid >> 2, pB = tid & 3;
    const size_t aRow = (size_t)(e * T_TOK + m0 + rA) * 512;
    const size_t dwb  = (size_t)e * (I_DIM * H_DIM / 2);

#define DN_ISSUE(s_) do { if ((s_) < N_ITERS) {                                              \
    uint32_t bb = dbase + ((s_) % STAGES) * DN_STRIDE;                                       \
    const uint32_t* ga = g_act_f16 + aRow + (s_) * 32 + hA * 16;                             \
    _Pragma("unroll") for (int q = 0; q < 4; q++)                                            \
        CP16(bb + DN_A + swz128(rA * 128 + hA * 64 + q * 16), ga + q * 4);                   \
    size_t bro = dwb + (size_t)((s_) * 64 + kB) * 512 + (n0 >> 1);                           \
    _Pragma("unroll") for (int h = 0; h < 2; h++)                                            \
        CP16(bb + DN_B + swz128(kB * 128 + (pB + h * 4) * 16), g_dwn_f16 + bro + (pB + h * 4) * 4); \
} CP_COMMIT(); } while (0)

    float cd[2][4][4];
#pragma unroll
    for (int a = 0; a < 2; a++)
#pragma unroll
        for (int b = 0; b < 4; b++)
#pragma unroll
            for (int c = 0; c < 4; c++) cd[a][b][c] = 0.f;

    DN_ISSUE(0);
    DN_ISSUE(1);

#pragma unroll 1
    for (int it = 0; it < N_ITERS; ++it) {
        CP_WAIT1();
        __syncthreads();
        DN_ISSUE(it + 2);
        uint32_t base = dbase + (it % STAGES) * DN_STRIDE;
#pragma unroll
        for (int s = 0; s < 4; s++) {
            uint32_t am[2][4];
#pragma unroll
            for (int mt = 0; mt < 2; mt++) {
                uint32_t row = mw * 32 + mt * 16 + (lane & 15);
                uint32_t co  = s * 32 + ((lane >> 4) << 4);
                ldsm4(am[mt], base + DN_A + swz128(row * 128 + co));
            }
            uint32_t krow = s * 16 + (lane & 15);
            uint32_t ccol = nw * 64 + ((lane >> 4) << 4);
            uint32_t bb[8];
#pragma unroll
            for (int h = 0; h < 2; h++)
                ldsm4t(bb + 4 * h, base + DN_B + swz128(krow * 128 + ccol + h * 32));
#pragma unroll
            for (int mt = 0; mt < 2; mt++)
#pragma unroll
                for (int nf = 0; nf < 4; nf++)
                    mma16816(cd[mt][nf], am[mt], bb[2*nf], bb[2*nf+1]);
        }
    }
#undef DN_ISSUE

    const float* db = dnb + e * H_DIM;
#pragma unroll
    for (int mt = 0; mt < 2; mt++)
#pragma unroll
        for (int r = 0; r < 2; r++) {
            int slot = m0 + mw * 32 + mt * 16 + (lane >> 2) + r * 8;
            if (slot >= cnt) continue;
            int   tok = g_tok[e * T_TOK + slot];
            float w   = g_wt [e * T_TOK + slot];
            float* op = out + (size_t)tok * H_DIM;
#pragma unroll
            for (int nf = 0; nf < 4; nf++) {
                int col = n0 + nw * 32 + nf * 8 + (lane & 3) * 2;
                float v0 = (cd[mt][nf][2 * r]     + db[col])     * w;
                float v1 = (cd[mt][nf][2 * r + 1] + db[col + 1]) * w;
                atomicAdd(op + col,     v0);
                atomicAdd(op + col + 1, v1);
            }
        }
}

// ---------------- launch -----------------------------------------------------
extern "C" void kernel_launch(void* const* d_in, const int* in_sizes, int n_in,
                              void* d_out, int out_size) {
    const float* x   = (const float*)d_in[0];
    const float* rw  = (const float*)d_in[1];
    const float* rb  = (const float*)d_in[2];
    const float* gup = (const float*)d_in[3];
    const float* gub = (const float*)d_in[4];
    const float* dwn = (const float*)d_in[5];
    const float* dnb = (const float*)d_in[6];
    float* out = (float*)d_out;

    static bool attr_done = false;
    if (!attr_done) {
        cudaFuncSetAttribute(moe_gateup_hmma, cudaFuncAttributeMaxDynamicSharedMemorySize,
                             STAGES * GU_STRIDE + 1024);
        cudaFuncSetAttribute(moe_down_hmma, cudaFuncAttributeMaxDynamicSharedMemorySize,
                             STAGES * DN_STRIDE + 1024);
        attr_done = true;
    }

    uint32_t *xf, *gf, *df;
    cudaGetSymbolAddress((void**)&xf, g_x_f16);
    cudaGetSymbolAddress((void**)&gf, g_gup_f16);
    cudaGetSymbolAddress((void**)&df, g_dwn_f16);

    zero_kernel<<<(T_TOK * H_DIM / 4 + 255) / 256, 256>>>((float4*)out);

    int n4x = T_TOK * H_DIM / 4;
    convert_kernel<<<(n4x / 2 + 255) / 256, 256>>>((const float4*)x, (uint2*)xf, n4x);
    int n4g = N_EXP * H_DIM * 2 * I_DIM / 4;
    convert_kernel<<<(n4g / 2 + 255) / 256, 256>>>((const float4*)gup, (uint2*)gf, n4g);
    int n4d = N_EXP * I_DIM * H_DIM / 4;
    convert_kernel<<<(n4d / 2 + 255) / 256, 256>>>((const float4*)dwn, (uint2*)df, n4d);

    router_kernel<<<T_TOK, 128>>>(x, rw, rb);

    dim3 g1(T_TOK / 128, I_DIM / 64, N_EXP);
    moe_gateup_hmma<<<g1, 256, STAGES * GU_STRIDE + 1024>>>(gub);

    dim3 g2(T_TOK / 128, H_DIM / 64, N_EXP);
    moe_down_hmma<<<g2, 256, STAGES * DN_STRIDE + 1024>>>(dnb, out);
}

// round 9
// speedup vs baseline: 1.1685x; 1.1685x over previous
#include <cuda_runtime.h>
#include <cstdint>
#include <math.h>

#define T_TOK 1024
#define H_DIM 1024
#define N_EXP 8
#define I_DIM 1024
#define ALPHA 1.702f
#define LIMIT 7.0f

// ---------------- device scratch (no allocations allowed) --------------------
__device__ int      g_cnt[N_EXP];
__device__ int      g_tok[N_EXP * T_TOK];
__device__ float    g_wt [N_EXP * T_TOK];
// fp16 operand planes, packed 2 elems per u32
__device__ __align__(16) uint32_t g_x_f16  [(size_t)T_TOK * H_DIM / 2];
__device__ __align__(16) uint32_t g_gup_f16[(size_t)N_EXP * H_DIM * 2 * I_DIM / 2];
__device__ __align__(16) uint32_t g_dwn_f16[(size_t)N_EXP * I_DIM * H_DIM / 2];
__device__ __align__(16) uint32_t g_act_f16[(size_t)N_EXP * T_TOK * I_DIM / 2];

// ---------------- helpers ----------------------------------------------------
__device__ __forceinline__ uint32_t smem_u32(const void* p) {
    uint32_t a;
    asm("{ .reg .u64 t; cvta.to.shared.u64 t, %1; cvt.u32.u64 %0, t; }"
        : "=r"(a) : "l"(p));
    return a;
}
__device__ __forceinline__ uint32_t swz128(uint32_t off) { return off ^ ((off >> 3) & 0x70); }
__device__ __forceinline__ uint32_t swz64 (uint32_t off) { return off ^ ((off >> 3) & 0x30); }

__device__ __forceinline__ uint32_t pack_f16x2(float a, float b) {
    uint32_t r;
    asm("cvt.rn.f16x2.f32 %0, %1, %2;" : "=r"(r) : "f"(b), "f"(a));  // a -> low half
    return r;
}

__device__ __forceinline__ void ldsm4(uint32_t* r, uint32_t a) {
    asm volatile("ldmatrix.sync.aligned.m8n8.x4.shared.b16 {%0,%1,%2,%3}, [%4];"
        : "=r"(r[0]), "=r"(r[1]), "=r"(r[2]), "=r"(r[3]) : "r"(a));
}
__device__ __forceinline__ void ldsm4t(uint32_t* r, uint32_t a) {
    asm volatile("ldmatrix.sync.aligned.m8n8.x4.trans.shared.b16 {%0,%1,%2,%3}, [%4];"
        : "=r"(r[0]), "=r"(r[1]), "=r"(r[2]), "=r"(r[3]) : "r"(a));
}
__device__ __forceinline__ void mma16816(float* c, const uint32_t* a, uint32_t b0, uint32_t b1) {
    asm volatile("mma.sync.aligned.m16n8k16.row.col.f32.f16.f16.f32 "
        "{%0,%1,%2,%3}, {%4,%5,%6,%7}, {%8,%9}, {%0,%1,%2,%3};"
        : "+f"(c[0]), "+f"(c[1]), "+f"(c[2]), "+f"(c[3])
        : "r"(a[0]), "r"(a[1]), "r"(a[2]), "r"(a[3]), "r"(b0), "r"(b1));
}

#define CP16(dst, src) \
    asm volatile("cp.async.cg.shared.global [%0], [%1], 16;" :: "r"(dst), "l"(src) : "memory")
#define CP_COMMIT() asm volatile("cp.async.commit_group;" ::: "memory")
#define CP_WAIT2()  asm volatile("cp.async.wait_group 2;" ::: "memory")

// ---------------- fused convert: fp32 -> packed fp16 (32B/thread) ------------
// ranges in "2x float4" units
#define NX2 (T_TOK * H_DIM / 8)
#define NG2 (N_EXP * H_DIM * 2 * I_DIM / 8)
#define ND2 (N_EXP * I_DIM * H_DIM / 8)

__global__ void convert_all(const float4* __restrict__ x,
                            const float4* __restrict__ gup,
                            const float4* __restrict__ dwn) {
    int i = blockIdx.x * blockDim.x + threadIdx.x;
    if (i < N_EXP) g_cnt[i] = 0;      // runs before router launch
    if (i >= NX2 + NG2 + ND2) return;
    const float4* src; uint2* dst; int j;
    if (i < NX2)            { src = x;   dst = (uint2*)g_x_f16;   j = i; }
    else if (i < NX2 + NG2) { src = gup; dst = (uint2*)g_gup_f16; j = i - NX2; }
    else                    { src = dwn; dst = (uint2*)g_dwn_f16; j = i - NX2 - NG2; }
    j *= 2;
    float4 v0 = src[j];
    float4 v1 = src[j + 1];
    dst[j]     = make_uint2(pack_f16x2(v0.x, v0.y), pack_f16x2(v0.z, v0.w));
    dst[j + 1] = make_uint2(pack_f16x2(v1.x, v1.y), pack_f16x2(v1.z, v1.w));
}

// ---------------- router (also zeroes its token's output row) ----------------
__global__ void router_kernel(const float* __restrict__ x,
                              const float* __restrict__ rw,
                              const float* __restrict__ rb,
                              float4* __restrict__ out) {
    const int t = blockIdx.x;
    // zero out[t][:] : 256 float4 by 128 threads
    float4 z4 = make_float4(0.f, 0.f, 0.f, 0.f);
    out[t * 256 + threadIdx.x]       = z4;
    out[t * 256 + threadIdx.x + 128] = z4;

    __shared__ float s[N_EXP][128];
    float p[N_EXP];
#pragma unroll
    for (int e = 0; e < N_EXP; e++) p[e] = 0.0f;
    const float* xr = x + (size_t)t * H_DIM;
    for (int h = threadIdx.x; h < H_DIM; h += 128) {
        float xv = xr[h];
#pragma unroll
        for (int e = 0; e < N_EXP; e++) p[e] += xv * rw[e * H_DIM + h];
    }
#pragma unroll
    for (int e = 0; e < N_EXP; e++) s[e][threadIdx.x] = p[e];
    __syncthreads();
    if (threadIdx.x == 0) {
        float l[N_EXP], mx = -1e30f;
#pragma unroll
        for (int e = 0; e < N_EXP; e++) {
            float sum = 0.0f;
            for (int i = 0; i < 128; i++) sum += s[e][i];
            l[e] = sum + rb[e];
            mx = fmaxf(mx, l[e]);
        }
        float den = 0.0f, sc[N_EXP];
#pragma unroll
        for (int e = 0; e < N_EXP; e++) { sc[e] = expf(l[e] - mx); den += sc[e]; }
        float inv = 1.0f / den;
#pragma unroll
        for (int e = 0; e < N_EXP; e++) sc[e] *= inv;
        int i0 = 0;
#pragma unroll
        for (int e = 1; e < N_EXP; e++) if (sc[e] > sc[i0]) i0 = e;
        int i1 = (i0 == 0) ? 1 : 0;
#pragma unroll
        for (int e = 0; e < N_EXP; e++) if (e != i0 && sc[e] > sc[i1]) i1 = e;
        int p0 = atomicAdd(&g_cnt[i0], 1);
        g_tok[i0 * T_TOK + p0] = t; g_wt[i0 * T_TOK + p0] = sc[i0];
        int p1 = atomicAdd(&g_cnt[i1], 1);
        g_tok[i1 * T_TOK + p1] = t; g_wt[i1 * T_TOK + p1] = sc[i1];
    }
}

// ---------------- kernel 2: gate_up HMMA (fp16, BK=32, 4-stage) --------------
// Stage (16KB): A 8KB (128 rows x 64B, SW64), BG 4KB, BU 4KB (32 k-rows x 128B, SW128)
#define GU_A      0
#define GU_BG     8192
#define GU_BU     12288
#define GU_STRIDE 16384
#define STAGES    4
#define N_ITERS   32

__global__ __launch_bounds__(256, 2)
void moe_gateup_hmma(const float* __restrict__ gub) {
    const int e   = blockIdx.z;
    const int cnt = g_cnt[e];
    const int m0  = blockIdx.x * 128;
    if (m0 >= cnt) return;
    const int n0  = blockIdx.y * 64;

    extern __shared__ char dsm[];
    __shared__ int s_tok[128];
    const uint32_t dbase = (smem_u32(dsm) + 1023u) & ~1023u;

    const int tid = threadIdx.x, lane = tid & 31, wid = tid >> 5;
    const int mw = wid >> 1, nw = wid & 1;

    if (tid < 128) {
        int gm = m0 + tid;
        s_tok[tid] = (gm < cnt) ? g_tok[e * T_TOK + gm] : g_tok[e * T_TOK];
    }
    __syncthreads();

    const int rA = tid >> 2, pA = tid & 3;       // A: rows rA, rA+64; 16B chunk pA
    const int tA0 = s_tok[rA], tA1 = s_tok[rA + 64];
    const int kB = tid >> 3, pB = tid & 7;       // B: k-row kB; 16B chunk pB
    const size_t gupb = (size_t)e * (H_DIM * I_DIM);      // u32; row stride 1024
    const uint32_t dA0 = swz64(rA * 64 + pA * 16);
    const uint32_t dA1 = swz64((rA + 64) * 64 + pA * 16);
    const uint32_t dB  = swz128(kB * 128 + pB * 16);

#define GU_ISSUE(s_) do { if ((s_) < N_ITERS) {                                              \
    uint32_t bb = dbase + ((s_) % STAGES) * GU_STRIDE;                                       \
    int kh = (s_) * 16;                                                                      \
    CP16(bb + GU_A + dA0, g_x_f16 + (size_t)tA0 * 512 + kh + pA * 4);                        \
    CP16(bb + GU_A + dA1, g_x_f16 + (size_t)tA1 * 512 + kh + pA * 4);                        \
    size_t bro = gupb + (size_t)((s_) * 32 + kB) * 1024 + (n0 >> 1) + pB * 4;                \
    CP16(bb + GU_BG + dB, g_gup_f16 + bro);                                                  \
    CP16(bb + GU_BU + dB, g_gup_f16 + bro + 512);                                            \
} CP_COMMIT(); } while (0)

    float cg[2][4][4], cu[2][4][4];
#pragma unroll
    for (int a = 0; a < 2; a++)
#pragma unroll
        for (int b = 0; b < 4; b++)
#pragma unroll
            for (int c = 0; c < 4; c++) { cg[a][b][c] = 0.f; cu[a][b][c] = 0.f; }

    GU_ISSUE(0);
    GU_ISSUE(1);

#pragma unroll 1
    for (int it = 0; it < N_ITERS; ++it) {
        GU_ISSUE(it + 2);
        CP_WAIT2();
        __syncthreads();
        uint32_t base = dbase + (it % STAGES) * GU_STRIDE;
#pragma unroll
        for (int s = 0; s < 2; s++) {
            uint32_t am[2][4];
#pragma unroll
            for (int mt = 0; mt < 2; mt++) {
                uint32_t row = mw * 32 + mt * 16 + (lane & 15);
                uint32_t co  = s * 32 + ((lane >> 4) << 4);
                ldsm4(am[mt], base + GU_A + swz64(row * 64 + co));
            }
            uint32_t krow = s * 16 + (lane & 15);
            uint32_t ccol = nw * 64 + ((lane >> 4) << 4);
            uint32_t bg[8], bu[8];
#pragma unroll
            for (int h = 0; h < 2; h++) {
                ldsm4t(bg + 4 * h, base + GU_BG + swz128(krow * 128 + ccol + h * 32));
                ldsm4t(bu + 4 * h, base + GU_BU + swz128(krow * 128 + ccol + h * 32));
            }
#pragma unroll
            for (int mt = 0; mt < 2; mt++)
#pragma unroll
                for (int nf = 0; nf < 4; nf++) {
                    mma16816(cg[mt][nf], am[mt], bg[2*nf], bg[2*nf+1]);
                    mma16816(cu[mt][nf], am[mt], bu[2*nf], bu[2*nf+1]);
                }
        }
        __syncthreads();
    }
#undef GU_ISSUE

    // epilogue: bias + clamped GLU -> g_act (packed fp16)
    const float* gb = gub + e * 2 * I_DIM;
#pragma unroll
    for (int mt = 0; mt < 2; mt++)
#pragma unroll
        for (int r = 0; r < 2; r++) {
            int slot = m0 + mw * 32 + mt * 16 + (lane >> 2) + r * 8;
            if (slot >= cnt) continue;
            size_t abase = ((size_t)(e * T_TOK + slot) * I_DIM) >> 1;
#pragma unroll
            for (int nf = 0; nf < 4; nf++) {
                int col = n0 + nw * 32 + nf * 8 + (lane & 3) * 2;
                float g0 = cg[mt][nf][2 * r]     + gb[col];
                float g1 = cg[mt][nf][2 * r + 1] + gb[col + 1];
                float u0 = cu[mt][nf][2 * r]     + gb[I_DIM + col];
                float u1 = cu[mt][nf][2 * r + 1] + gb[I_DIM + col + 1];
                g0 = fminf(g0, LIMIT); g1 = fminf(g1, LIMIT);
                u0 = fminf(fmaxf(u0, -LIMIT), LIMIT);
                u1 = fminf(fmaxf(u1, -LIMIT), LIMIT);
                float a0 = (u0 + 1.0f) * (g0 / (1.0f + __expf(-ALPHA * g0)));
                float a1 = (u1 + 1.0f) * (g1 / (1.0f + __expf(-ALPHA * g1)));
                g_act_f16[abase + (col >> 1)] = pack_f16x2(a0, a1);
            }
        }
}

// ---------------- kernel 3: down HMMA (fp16, BK=32, 4-stage) -----------------
// Stage (12KB): A 8KB (SW64), B 4KB (SW128)
#define DN_A      0
#define DN_B      8192
#define DN_STRIDE 12288

__global__ __launch_bounds__(256, 2)
void moe_down_hmma(const float* __restrict__ dnb, float* __restrict__ out) {
    const int e   = blockIdx.z;
    const int cnt = g_cnt[e];
    const int m0  = blockIdx.x * 128;
    if (m0 >= cnt) return;
    const int n0  = blockIdx.y * 64;

    extern __shared__ char dsm[];
    const uint32_t dbase = (smem_u32(dsm) + 1023u) & ~1023u;

    const int tid = threadIdx.x, lane = tid & 31, wid = tid >> 5;
    const int mw = wid >> 1, nw = wid & 1;

    const int rA = tid >> 2, pA = tid & 3;
    const int kB = tid >> 3, pB = tid & 7;
    const size_t a0 = (size_t)(e * T_TOK + m0 + rA) * 512;
    const size_t a1 = (size_t)(e * T_TOK + m0 + rA + 64) * 512;
    const size_t dwb = (size_t)e * (I_DIM * H_DIM / 2);
    const uint32_t dA0 = swz64(rA * 64 + pA * 16);
    const uint32_t dA1 = swz64((rA + 64) * 64 + pA * 16);
    const uint32_t dB  = swz128(kB * 128 + pB * 16);

#define DN_ISSUE(s_) do { if ((s_) < N_ITERS) {                                              \
    uint32_t bb = dbase + ((s_) % STAGES) * DN_STRIDE;                                       \
    int kh = (s_) * 16;                                                                      \
    CP16(bb + DN_A + dA0, g_act_f16 + a0 + kh + pA * 4);                                     \
    CP16(bb + DN_A + dA1, g_act_f16 + a1 + kh + pA * 4);                                     \
    size_t bro = dwb + (size_t)((s_) * 32 + kB) * 512 + (n0 >> 1) + pB * 4;                  \
    CP16(bb + DN_B + dB, g_dwn_f16 + bro);                                                   \
} CP_COMMIT(); } while (0)

    float cd[2][4][4];
#pragma unroll
    for (int a = 0; a < 2; a++)
#pragma unroll
        for (int b = 0; b < 4; b++)
#pragma unroll
            for (int c = 0; c < 4; c++) cd[a][b][c] = 0.f;

    DN_ISSUE(0);
    DN_ISSUE(1);

#pragma unroll 1
    for (int it = 0; it < N_ITERS; ++it) {
        DN_ISSUE(it + 2);
        CP_WAIT2();
        __syncthreads();
        uint32_t base = dbase + (it % STAGES) * DN_STRIDE;
#pragma unroll
        for (int s = 0; s < 2; s++) {
            uint32_t am[2][4];
#pragma unroll
            for (int mt = 0; mt < 2; mt++) {
                uint32_t row = mw * 32 + mt * 16 + (lane & 15);
                uint32_t co  = s * 32 + ((lane >> 4) << 4);
                ldsm4(am[mt], base + DN_A + swz64(row * 64 + co));
            }
            uint32_t krow = s * 16 + (lane & 15);
            uint32_t ccol = nw * 64 + ((lane >> 4) << 4);
            uint32_t bb[8];
#pragma unroll
            for (int h = 0; h < 2; h++)
                ldsm4t(bb + 4 * h, base + DN_B + swz128(krow * 128 + ccol + h * 32));
#pragma unroll
            for (int mt = 0; mt < 2; mt++)
#pragma unroll
                for (int nf = 0; nf < 4; nf++)
                    mma16816(cd[mt][nf], am[mt], bb[2*nf], bb[2*nf+1]);
        }
        __syncthreads();
    }
#undef DN_ISSUE

    const float* db = dnb + e * H_DIM;
#pragma unroll
    for (int mt = 0; mt < 2; mt++)
#pragma unroll
        for (int r = 0; r < 2; r++) {
            int slot = m0 + mw * 32 + mt * 16 + (lane >> 2) + r * 8;
            if (slot >= cnt) continue;
            int   tok = g_tok[e * T_TOK + slot];
            float w   = g_wt [e * T_TOK + slot];
            float* op = out + (size_t)tok * H_DIM;
#pragma unroll
            for (int nf = 0; nf < 4; nf++) {
                int col = n0 + nw * 32 + nf * 8 + (lane & 3) * 2;
                float v0 = (cd[mt][nf][2 * r]     + db[col])     * w;
                float v1 = (cd[mt][nf][2 * r + 1] + db[col + 1]) * w;
                atomicAdd(op + col,     v0);
                atomicAdd(op + col + 1, v1);
            }
        }
}

// ---------------- launch -----------------------------------------------------
extern "C" void kernel_launch(void* const* d_in, const int* in_sizes, int n_in,
                              void* d_out, int out_size) {
    const float* x   = (const float*)d_in[0];
    const float* rw  = (const float*)d_in[1];
    const float* rb  = (const float*)d_in[2];
    const float* gup = (const float*)d_in[3];
    const float* gub = (const float*)d_in[4];
    const float* dwn = (const float*)d_in[5];
    const float* dnb = (const float*)d_in[6];
    float* out = (float*)d_out;

    static bool attr_done = false;
    if (!attr_done) {
        cudaFuncSetAttribute(moe_gateup_hmma, cudaFuncAttributeMaxDynamicSharedMemorySize,
                             STAGES * GU_STRIDE + 1024);
        cudaFuncSetAttribute(moe_down_hmma, cudaFuncAttributeMaxDynamicSharedMemorySize,
                             STAGES * DN_STRIDE + 1024);
        attr_done = true;
    }

    int n2 = NX2 + NG2 + ND2;
    convert_all<<<(n2 + 255) / 256, 256>>>((const float4*)x, (const float4*)gup,
                                           (const float4*)dwn);

    router_kernel<<<T_TOK, 128>>>(x, rw, rb, (float4*)out);

    dim3 g1(T_TOK / 128, I_DIM / 64, N_EXP);
    moe_gateup_hmma<<<g1, 256, STAGES * GU_STRIDE + 1024>>>(gub);

    dim3 g2(T_TOK / 128, H_DIM / 64, N_EXP);
    moe_down_hmma<<<g2, 256, STAGES * DN_STRIDE + 1024>>>(dnb, out);
}

// round 10
// speedup vs baseline: 1.2449x; 1.0654x over previous
#include <cuda_runtime.h>
#include <cstdint>
#include <math.h>

#define T_TOK 1024
#define H_DIM 1024
#define N_EXP 8
#define I_DIM 1024
#define ALPHA 1.702f
#define LIMIT 7.0f

// ---------------- device scratch (no allocations allowed) --------------------
__device__ int      g_cnt[N_EXP];
__device__ int      g_tok[N_EXP * T_TOK];
__device__ float    g_wt [N_EXP * T_TOK];
// fp16 operand planes, packed 2 elems per u32
__device__ __align__(16) uint32_t g_x_f16  [(size_t)T_TOK * H_DIM / 2];
__device__ __align__(16) uint32_t g_gup_f16[(size_t)N_EXP * H_DIM * 2 * I_DIM / 2];
__device__ __align__(16) uint32_t g_dwn_f16[(size_t)N_EXP * I_DIM * H_DIM / 2];
__device__ __align__(16) uint32_t g_act_f16[(size_t)N_EXP * T_TOK * I_DIM / 2];

// ---------------- helpers ----------------------------------------------------
__device__ __forceinline__ uint32_t smem_u32(const void* p) {
    uint32_t a;
    asm("{ .reg .u64 t; cvta.to.shared.u64 t, %1; cvt.u32.u64 %0, t; }"
        : "=r"(a) : "l"(p));
    return a;
}
__device__ __forceinline__ uint32_t swz128(uint32_t off) { return off ^ ((off >> 3) & 0x70); }
__device__ __forceinline__ uint32_t swz64 (uint32_t off) { return off ^ ((off >> 3) & 0x30); }

__device__ __forceinline__ uint32_t pack_f16x2(float a, float b) {
    uint32_t r;
    asm("cvt.rn.f16x2.f32 %0, %1, %2;" : "=r"(r) : "f"(b), "f"(a));  // a -> low half
    return r;
}

__device__ __forceinline__ void ldsm4(uint32_t* r, uint32_t a) {
    asm volatile("ldmatrix.sync.aligned.m8n8.x4.shared.b16 {%0,%1,%2,%3}, [%4];"
        : "=r"(r[0]), "=r"(r[1]), "=r"(r[2]), "=r"(r[3]) : "r"(a));
}
__device__ __forceinline__ void ldsm4t(uint32_t* r, uint32_t a) {
    asm volatile("ldmatrix.sync.aligned.m8n8.x4.trans.shared.b16 {%0,%1,%2,%3}, [%4];"
        : "=r"(r[0]), "=r"(r[1]), "=r"(r[2]), "=r"(r[3]) : "r"(a));
}
__device__ __forceinline__ void mma16816(float* c, const uint32_t* a, uint32_t b0, uint32_t b1) {
    asm volatile("mma.sync.aligned.m16n8k16.row.col.f32.f16.f16.f32 "
        "{%0,%1,%2,%3}, {%4,%5,%6,%7}, {%8,%9}, {%0,%1,%2,%3};"
        : "+f"(c[0]), "+f"(c[1]), "+f"(c[2]), "+f"(c[3])
        : "r"(a[0]), "r"(a[1]), "r"(a[2]), "r"(a[3]), "r"(b0), "r"(b1));
}

#define CP16(dst, src) \
    asm volatile("cp.async.cg.shared.global [%0], [%1], 16;" :: "r"(dst), "l"(src) : "memory")
#define CP_COMMIT() asm volatile("cp.async.commit_group;" ::: "memory")
#define CP_WAIT3()  asm volatile("cp.async.wait_group 3;" ::: "memory")

// ---------------- fused prologue: router + fp32->fp16 converts ---------------
// grid = T_TOK router blocks first (overlap with BW-bound convert), then
// convert blocks. g_cnt is zeroed by cudaMemsetAsync before this kernel.
#define NX2 (T_TOK * H_DIM / 8)
#define NG2 (N_EXP * H_DIM * 2 * I_DIM / 8)
#define ND2 (N_EXP * I_DIM * H_DIM / 8)
#define NCV ((NX2 + NG2 + ND2 + 255) / 256)

__global__ void prologue_kernel(const float4* __restrict__ x4,
                                const float4* __restrict__ gup,
                                const float4* __restrict__ dwn,
                                const float* __restrict__ rw,
                                const float* __restrict__ rb,
                                float4* __restrict__ out) {
    const int tid = threadIdx.x;
    if (blockIdx.x < T_TOK) {
        // ---- router for token t (256 threads) + zero out row ----
        const int t = blockIdx.x;
        out[t * 256 + tid] = make_float4(0.f, 0.f, 0.f, 0.f);

        __shared__ float s[N_EXP][256];
        __shared__ float s_log[N_EXP];
        const float* xr = (const float*)(x4) + (size_t)t * H_DIM;
        float p[N_EXP];
#pragma unroll
        for (int e = 0; e < N_EXP; e++) p[e] = 0.0f;
#pragma unroll
        for (int q = 0; q < 4; q++) {
            int h = tid + q * 256;
            float xv = xr[h];
#pragma unroll
            for (int e = 0; e < N_EXP; e++) p[e] += xv * rw[e * H_DIM + h];
        }
#pragma unroll
        for (int e = 0; e < N_EXP; e++) s[e][tid] = p[e];
        __syncthreads();
        const int wid = tid >> 5, lane = tid & 31;
        {   // warp wid reduces expert wid
            float v = 0.0f;
#pragma unroll
            for (int j = 0; j < 8; j++) v += s[wid][lane + 32 * j];
#pragma unroll
            for (int o = 16; o > 0; o >>= 1) v += __shfl_xor_sync(0xFFFFFFFFu, v, o);
            if (lane == 0) s_log[wid] = v + rb[wid];
        }
        __syncthreads();
        if (tid == 0) {
            float l[N_EXP], mx = -1e30f;
#pragma unroll
            for (int e = 0; e < N_EXP; e++) { l[e] = s_log[e]; mx = fmaxf(mx, l[e]); }
            float den = 0.0f, sc[N_EXP];
#pragma unroll
            for (int e = 0; e < N_EXP; e++) { sc[e] = expf(l[e] - mx); den += sc[e]; }
            float inv = 1.0f / den;
#pragma unroll
            for (int e = 0; e < N_EXP; e++) sc[e] *= inv;
            int i0 = 0;
#pragma unroll
            for (int e = 1; e < N_EXP; e++) if (sc[e] > sc[i0]) i0 = e;
            int i1 = (i0 == 0) ? 1 : 0;
#pragma unroll
            for (int e = 0; e < N_EXP; e++) if (e != i0 && sc[e] > sc[i1]) i1 = e;
            int p0 = atomicAdd(&g_cnt[i0], 1);
            g_tok[i0 * T_TOK + p0] = t; g_wt[i0 * T_TOK + p0] = sc[i0];
            int p1 = atomicAdd(&g_cnt[i1], 1);
            g_tok[i1 * T_TOK + p1] = t; g_wt[i1 * T_TOK + p1] = sc[i1];
        }
        return;
    }
    // ---- convert: 32B of fp32 -> 16B of fp16 per thread ----
    int i = (blockIdx.x - T_TOK) * 256 + tid;
    if (i >= NX2 + NG2 + ND2) return;
    const float4* src; uint2* dst; int j;
    if (i < NX2)            { src = x4;  dst = (uint2*)g_x_f16;   j = i; }
    else if (i < NX2 + NG2) { src = gup; dst = (uint2*)g_gup_f16; j = i - NX2; }
    else                    { src = dwn; dst = (uint2*)g_dwn_f16; j = i - NX2 - NG2; }
    j *= 2;
    float4 v0 = src[j];
    float4 v1 = src[j + 1];
    dst[j]     = make_uint2(pack_f16x2(v0.x, v0.y), pack_f16x2(v0.z, v0.w));
    dst[j + 1] = make_uint2(pack_f16x2(v1.x, v1.y), pack_f16x2(v1.z, v1.w));
}

// ---------------- kernel 2: gate_up HMMA (fp16, BK=32, 4-stage, depth-3) -----
// Stage (16KB): A 8KB (128 rows x 64B, SW64), BG 4KB, BU 4KB (32 k-rows x 128B, SW128)
#define GU_A      0
#define GU_BG     8192
#define GU_BU     12288
#define GU_STRIDE 16384
#define STAGES    4
#define N_ITERS   32

__global__ __launch_bounds__(256, 2)
void moe_gateup_hmma(const float* __restrict__ gub) {
    const int e   = blockIdx.z;
    const int cnt = g_cnt[e];
    const int m0  = blockIdx.x * 128;
    if (m0 >= cnt) return;
    const int n0  = blockIdx.y * 64;

    extern __shared__ char dsm[];
    __shared__ int s_tok[128];
    const uint32_t dbase = (smem_u32(dsm) + 1023u) & ~1023u;

    const int tid = threadIdx.x, lane = tid & 31, wid = tid >> 5;
    const int mw = wid >> 1, nw = wid & 1;

    if (tid < 128) {
        int gm = m0 + tid;
        s_tok[tid] = (gm < cnt) ? g_tok[e * T_TOK + gm] : g_tok[e * T_TOK];
    }
    __syncthreads();

    const int rA = tid >> 2, pA = tid & 3;       // A: rows rA, rA+64; 16B chunk pA
    const int tA0 = s_tok[rA], tA1 = s_tok[rA + 64];
    const int kB = tid >> 3, pB = tid & 7;       // B: k-row kB; 16B chunk pB
    const size_t gupb = (size_t)e * (H_DIM * I_DIM);      // u32; row stride 1024
    const uint32_t dA0 = swz64(rA * 64 + pA * 16);
    const uint32_t dA1 = swz64((rA + 64) * 64 + pA * 16);
    const uint32_t dB  = swz128(kB * 128 + pB * 16);

#define GU_ISSUE(s_) do { if ((s_) < N_ITERS) {                                              \
    uint32_t bb = dbase + ((s_) % STAGES) * GU_STRIDE;                                       \
    int kh = (s_) * 16;                                                                      \
    CP16(bb + GU_A + dA0, g_x_f16 + (size_t)tA0 * 512 + kh + pA * 4);                        \
    CP16(bb + GU_A + dA1, g_x_f16 + (size_t)tA1 * 512 + kh + pA * 4);                        \
    size_t bro = gupb + (size_t)((s_) * 32 + kB) * 1024 + (n0 >> 1) + pB * 4;                \
    CP16(bb + GU_BG + dB, g_gup_f16 + bro);                                                  \
    CP16(bb + GU_BU + dB, g_gup_f16 + bro + 512);                                            \
} CP_COMMIT(); } while (0)

    float cg[2][4][4], cu[2][4][4];
#pragma unroll
    for (int a = 0; a < 2; a++)
#pragma unroll
        for (int b = 0; b < 4; b++)
#pragma unroll
            for (int c = 0; c < 4; c++) { cg[a][b][c] = 0.f; cu[a][b][c] = 0.f; }

    GU_ISSUE(0);
    GU_ISSUE(1);
    GU_ISSUE(2);

#pragma unroll 1
    for (int it = 0; it < N_ITERS; ++it) {
        GU_ISSUE(it + 3);
        CP_WAIT3();
        __syncthreads();
        uint32_t base = dbase + (it % STAGES) * GU_STRIDE;
#pragma unroll
        for (int s = 0; s < 2; s++) {
            uint32_t am[2][4];
#pragma unroll
            for (int mt = 0; mt < 2; mt++) {
                uint32_t row = mw * 32 + mt * 16 + (lane & 15);
                uint32_t co  = s * 32 + ((lane >> 4) << 4);
                ldsm4(am[mt], base + GU_A + swz64(row * 64 + co));
            }
            uint32_t krow = s * 16 + (lane & 15);
            uint32_t ccol = nw * 64 + ((lane >> 4) << 4);
            uint32_t bg[8], bu[8];
#pragma unroll
            for (int h = 0; h < 2; h++) {
                ldsm4t(bg + 4 * h, base + GU_BG + swz128(krow * 128 + ccol + h * 32));
                ldsm4t(bu + 4 * h, base + GU_BU + swz128(krow * 128 + ccol + h * 32));
            }
#pragma unroll
            for (int mt = 0; mt < 2; mt++)
#pragma unroll
                for (int nf = 0; nf < 4; nf++) {
                    mma16816(cg[mt][nf], am[mt], bg[2*nf], bg[2*nf+1]);
                    mma16816(cu[mt][nf], am[mt], bu[2*nf], bu[2*nf+1]);
                }
        }
        __syncthreads();
    }
#undef GU_ISSUE

    // epilogue: bias + clamped GLU -> g_act (packed fp16)
    const float* gb = gub + e * 2 * I_DIM;
#pragma unroll
    for (int mt = 0; mt < 2; mt++)
#pragma unroll
        for (int r = 0; r < 2; r++) {
            int slot = m0 + mw * 32 + mt * 16 + (lane >> 2) + r * 8;
            if (slot >= cnt) continue;
            size_t abase = ((size_t)(e * T_TOK + slot) * I_DIM) >> 1;
#pragma unroll
            for (int nf = 0; nf < 4; nf++) {
                int col = n0 + nw * 32 + nf * 8 + (lane & 3) * 2;
                float g0 = cg[mt][nf][2 * r]     + gb[col];
                float g1 = cg[mt][nf][2 * r + 1] + gb[col + 1];
                float u0 = cu[mt][nf][2 * r]     + gb[I_DIM + col];
                float u1 = cu[mt][nf][2 * r + 1] + gb[I_DIM + col + 1];
                g0 = fminf(g0, LIMIT); g1 = fminf(g1, LIMIT);
                u0 = fminf(fmaxf(u0, -LIMIT), LIMIT);
                u1 = fminf(fmaxf(u1, -LIMIT), LIMIT);
                float a0 = (u0 + 1.0f) * (g0 / (1.0f + __expf(-ALPHA * g0)));
                float a1 = (u1 + 1.0f) * (g1 / (1.0f + __expf(-ALPHA * g1)));
                g_act_f16[abase + (col >> 1)] = pack_f16x2(a0, a1);
            }
        }
}

// ---------------- kernel 3: down HMMA (fp16, BK=32, 4-stage, depth-3) --------
// Stage (12KB): A 8KB (SW64), B 4KB (SW128)
#define DN_A      0
#define DN_B      8192
#define DN_STRIDE 12288

__global__ __launch_bounds__(256, 2)
void moe_down_hmma(const float* __restrict__ dnb, float* __restrict__ out) {
    const int e   = blockIdx.z;
    const int cnt = g_cnt[e];
    const int m0  = blockIdx.x * 128;
    if (m0 >= cnt) return;
    const int n0  = blockIdx.y * 64;

    extern __shared__ char dsm[];
    const uint32_t dbase = (smem_u32(dsm) + 1023u) & ~1023u;

    const int tid = threadIdx.x, lane = tid & 31, wid = tid >> 5;
    const int mw = wid >> 1, nw = wid & 1;

    const int rA = tid >> 2, pA = tid & 3;
    const int kB = tid >> 3, pB = tid & 7;
    const size_t a0 = (size_t)(e * T_TOK + m0 + rA) * 512;
    const size_t a1 = (size_t)(e * T_TOK + m0 + rA + 64) * 512;
    const size_t dwb = (size_t)e * (I_DIM * H_DIM / 2);
    const uint32_t dA0 = swz64(rA * 64 + pA * 16);
    const uint32_t dA1 = swz64((rA + 64) * 64 + pA * 16);
    const uint32_t dB  = swz128(kB * 128 + pB * 16);

#define DN_ISSUE(s_) do { if ((s_) < N_ITERS) {                                              \
    uint32_t bb = dbase + ((s_) % STAGES) * DN_STRIDE;                                       \
    int kh = (s_) * 16;                                                                      \
    CP16(bb + DN_A + dA0, g_act_f16 + a0 + kh + pA * 4);                                     \
    CP16(bb + DN_A + dA1, g_act_f16 + a1 + kh + pA * 4);                                     \
    size_t bro = dwb + (size_t)((s_) * 32 + kB) * 512 + (n0 >> 1) + pB * 4;                  \
    CP16(bb + DN_B + dB, g_dwn_f16 + bro);                                                   \
} CP_COMMIT(); } while (0)

    float cd[2][4][4];
#pragma unroll
    for (int a = 0; a < 2; a++)
#pragma unroll
        for (int b = 0; b < 4; b++)
#pragma unroll
            for (int c = 0; c < 4; c++) cd[a][b][c] = 0.f;

    DN_ISSUE(0);
    DN_ISSUE(1);
    DN_ISSUE(2);

#pragma unroll 1
    for (int it = 0; it < N_ITERS; ++it) {
        DN_ISSUE(it + 3);
        CP_WAIT3();
        __syncthreads();
        uint32_t base = dbase + (it % STAGES) * DN_STRIDE;
#pragma unroll
        for (int s = 0; s < 2; s++) {
            uint32_t am[2][4];
#pragma unroll
            for (int mt = 0; mt < 2; mt++) {
                uint32_t row = mw * 32 + mt * 16 + (lane & 15);
                uint32_t co  = s * 32 + ((lane >> 4) << 4);
                ldsm4(am[mt], base + DN_A + swz64(row * 64 + co));
            }
            uint32_t krow = s * 16 + (lane & 15);
            uint32_t ccol = nw * 64 + ((lane >> 4) << 4);
            uint32_t bb[8];
#pragma unroll
            for (int h = 0; h < 2; h++)
                ldsm4t(bb + 4 * h, base + DN_B + swz128(krow * 128 + ccol + h * 32));
#pragma unroll
            for (int mt = 0; mt < 2; mt++)
#pragma unroll
                for (int nf = 0; nf < 4; nf++)
                    mma16816(cd[mt][nf], am[mt], bb[2*nf], bb[2*nf+1]);
        }
        __syncthreads();
    }
#undef DN_ISSUE

    const float* db = dnb + e * H_DIM;
#pragma unroll
    for (int mt = 0; mt < 2; mt++)
#pragma unroll
        for (int r = 0; r < 2; r++) {
            int slot = m0 + mw * 32 + mt * 16 + (lane >> 2) + r * 8;
            if (slot >= cnt) continue;
            int   tok = g_tok[e * T_TOK + slot];
            float w   = g_wt [e * T_TOK + slot];
            float* op = out + (size_t)tok * H_DIM;
#pragma unroll
            for (int nf = 0; nf < 4; nf++) {
                int col = n0 + nw * 32 + nf * 8 + (lane & 3) * 2;
                float v0 = (cd[mt][nf][2 * r]     + db[col])     * w;
                float v1 = (cd[mt][nf][2 * r + 1] + db[col + 1]) * w;
                atomicAdd(op + col,     v0);
                atomicAdd(op + col + 1, v1);
            }
        }
}

// ---------------- launch -----------------------------------------------------
extern "C" void kernel_launch(void* const* d_in, const int* in_sizes, int n_in,
                              void* d_out, int out_size) {
    const float* x   = (const float*)d_in[0];
    const float* rw  = (const float*)d_in[1];
    const float* rb  = (const float*)d_in[2];
    const float* gup = (const float*)d_in[3];
    const float* gub = (const float*)d_in[4];
    const float* dwn = (const float*)d_in[5];
    const float* dnb = (const float*)d_in[6];
    float* out = (float*)d_out;

    static bool attr_done = false;
    static void* cnt_addr = nullptr;
    if (!attr_done) {
        cudaFuncSetAttribute(moe_gateup_hmma, cudaFuncAttributeMaxDynamicSharedMemorySize,
                             STAGES * GU_STRIDE + 1024);
        cudaFuncSetAttribute(moe_down_hmma, cudaFuncAttributeMaxDynamicSharedMemorySize,
                             STAGES * DN_STRIDE + 1024);
        cudaGetSymbolAddress(&cnt_addr, g_cnt);
        attr_done = true;
    }

    cudaMemsetAsync(cnt_addr, 0, N_EXP * sizeof(int));

    prologue_kernel<<<T_TOK + NCV, 256>>>((const float4*)x, (const float4*)gup,
                                          (const float4*)dwn, rw, rb, (float4*)out);

    dim3 g1(T_TOK / 128, I_DIM / 64, N_EXP);
    moe_gateup_hmma<<<g1, 256, STAGES * GU_STRIDE + 1024>>>(gub);

    dim3 g2(T_TOK / 128, H_DIM / 64, N_EXP);
    moe_down_hmma<<<g2, 256, STAGES * DN_STRIDE + 1024>>>(dnb, out);
}

// round 12
// speedup vs baseline: 1.2666x; 1.0175x over previous
#include <cuda_runtime.h>
#include <cstdint>
#include <math.h>

#define T_TOK 1024
#define H_DIM 1024
#define N_EXP 8
#define I_DIM 1024
#define ALPHA 1.702f
#define LIMIT 7.0f

// ---------------- device scratch (no allocations allowed) --------------------
// g_cnt[0..7] = per-expert token counts, g_cnt[8] = convert ticket
__device__ int      g_cnt[16];
__device__ int      g_tok[N_EXP * T_TOK];
__device__ float    g_wt [N_EXP * T_TOK];
// fp16 operand planes, packed 2 elems per u32
__device__ __align__(16) uint32_t g_x_f16  [(size_t)T_TOK * H_DIM / 2];
__device__ __align__(16) uint32_t g_gup_f16[(size_t)N_EXP * H_DIM * 2 * I_DIM / 2];
__device__ __align__(16) uint32_t g_dwn_f16[(size_t)N_EXP * I_DIM * H_DIM / 2];
__device__ __align__(16) uint32_t g_act_f16[(size_t)N_EXP * T_TOK * I_DIM / 2];

// ---------------- helpers ----------------------------------------------------
__device__ __forceinline__ uint32_t smem_u32(const void* p) {
    uint32_t a;
    asm("{ .reg .u64 t; cvta.to.shared.u64 t, %1; cvt.u32.u64 %0, t; }"
        : "=r"(a) : "l"(p));
    return a;
}
__device__ __forceinline__ uint32_t swz128(uint32_t off) { return off ^ ((off >> 3) & 0x70); }
__device__ __forceinline__ uint32_t swz64 (uint32_t off) { return off ^ ((off >> 3) & 0x30); }

__device__ __forceinline__ uint32_t pack_f16x2(float a, float b) {
    uint32_t r;
    asm("cvt.rn.f16x2.f32 %0, %1, %2;" : "=r"(r) : "f"(b), "f"(a));  // a -> low half
    return r;
}

__device__ __forceinline__ void ldsm4(uint32_t* r, uint32_t a) {
    asm volatile("ldmatrix.sync.aligned.m8n8.x4.shared.b16 {%0,%1,%2,%3}, [%4];"
        : "=r"(r[0]), "=r"(r[1]), "=r"(r[2]), "=r"(r[3]) : "r"(a));
}
__device__ __forceinline__ void ldsm4t(uint32_t* r, uint32_t a) {
    asm volatile("ldmatrix.sync.aligned.m8n8.x4.trans.shared.b16 {%0,%1,%2,%3}, [%4];"
        : "=r"(r[0]), "=r"(r[1]), "=r"(r[2]), "=r"(r[3]) : "r"(a));
}
__device__ __forceinline__ void mma16816(float* c, const uint32_t* a, uint32_t b0, uint32_t b1) {
    asm volatile("mma.sync.aligned.m16n8k16.row.col.f32.f16.f16.f32 "
        "{%0,%1,%2,%3}, {%4,%5,%6,%7}, {%8,%9}, {%0,%1,%2,%3};"
        : "+f"(c[0]), "+f"(c[1]), "+f"(c[2]), "+f"(c[3])
        : "r"(a[0]), "r"(a[1]), "r"(a[2]), "r"(a[3]), "r"(b0), "r"(b1));
}

#define CP16(dst, src) \
    asm volatile("cp.async.cg.shared.global [%0], [%1], 16;" :: "r"(dst), "l"(src) : "memory")
#define CP_COMMIT() asm volatile("cp.async.commit_group;" ::: "memory")
#define CP_WAIT3()  asm volatile("cp.async.wait_group 3;" ::: "memory")

// sizes in "2x float4" (32B src) units
#define NX2 (T_TOK * H_DIM / 8)
#define NG2 (N_EXP * H_DIM * 2 * I_DIM / 8)
#define ND2 (N_EXP * I_DIM * H_DIM / 8)
#define NCV ((NX2 + NG2 + 255) / 256)
#define ND_CHUNKS (ND2 / 256)

// ---------------- fused prologue: router + x/gup converts --------------------
__global__ void prologue_kernel(const float4* __restrict__ x4,
                                const float4* __restrict__ gup,
                                const float* __restrict__ rw,
                                const float* __restrict__ rb,
                                float4* __restrict__ out) {
    const int tid = threadIdx.x;
    if (blockIdx.x < T_TOK) {
        // ---- router for token t (256 threads) + zero out row ----
        const int t = blockIdx.x;
        out[t * 256 + tid] = make_float4(0.f, 0.f, 0.f, 0.f);

        __shared__ float s[N_EXP][256];
        __shared__ float s_log[N_EXP];
        const float* xr = (const float*)(x4) + (size_t)t * H_DIM;
        float p[N_EXP];
#pragma unroll
        for (int e = 0; e < N_EXP; e++) p[e] = 0.0f;
#pragma unroll
        for (int q = 0; q < 4; q++) {
            int h = tid + q * 256;
            float xv = xr[h];
#pragma unroll
            for (int e = 0; e < N_EXP; e++) p[e] += xv * rw[e * H_DIM + h];
        }
#pragma unroll
        for (int e = 0; e < N_EXP; e++) s[e][tid] = p[e];
        __syncthreads();
        const int wid = tid >> 5, lane = tid & 31;
        {
            float v = 0.0f;
#pragma unroll
            for (int j = 0; j < 8; j++) v += s[wid][lane + 32 * j];
#pragma unroll
            for (int o = 16; o > 0; o >>= 1) v += __shfl_xor_sync(0xFFFFFFFFu, v, o);
            if (lane == 0) s_log[wid] = v + rb[wid];
        }
        __syncthreads();
        if (tid == 0) {
            float l[N_EXP], mx = -1e30f;
#pragma unroll
            for (int e = 0; e < N_EXP; e++) { l[e] = s_log[e]; mx = fmaxf(mx, l[e]); }
            float den = 0.0f, sc[N_EXP];
#pragma unroll
            for (int e = 0; e < N_EXP; e++) { sc[e] = expf(l[e] - mx); den += sc[e]; }
            float inv = 1.0f / den;
#pragma unroll
            for (int e = 0; e < N_EXP; e++) sc[e] *= inv;
            int i0 = 0;
#pragma unroll
            for (int e = 1; e < N_EXP; e++) if (sc[e] > sc[i0]) i0 = e;
            int i1 = (i0 == 0) ? 1 : 0;
#pragma unroll
            for (int e = 0; e < N_EXP; e++) if (e != i0 && sc[e] > sc[i1]) i1 = e;
            int p0 = atomicAdd(&g_cnt[i0], 1);
            g_tok[i0 * T_TOK + p0] = t; g_wt[i0 * T_TOK + p0] = sc[i0];
            int p1 = atomicAdd(&g_cnt[i1], 1);
            g_tok[i1 * T_TOK + p1] = t; g_wt[i1 * T_TOK + p1] = sc[i1];
        }
        return;
    }
    // ---- convert x + gate_up: 32B fp32 -> 16B fp16 per thread ----
    int i = (blockIdx.x - T_TOK) * 256 + tid;
    if (i >= NX2 + NG2) return;
    const float4* src; uint2* dst; int j;
    if (i < NX2) { src = x4;  dst = (uint2*)g_x_f16;   j = i; }
    else         { src = gup; dst = (uint2*)g_gup_f16; j = i - NX2; }
    j *= 2;
    float4 v0 = src[j];
    float4 v1 = src[j + 1];
    dst[j]     = make_uint2(pack_f16x2(v0.x, v0.y), pack_f16x2(v0.z, v0.w));
    dst[j + 1] = make_uint2(pack_f16x2(v1.x, v1.y), pack_f16x2(v1.z, v1.w));
}

// ---------------- kernel 2: gate_up HMMA (fp16, BK=32, 5-stage, depth-3) -----
// Stage (16KB): A 8KB (128 rows x 64B, SW64), BG 4KB, BU 4KB (32 k-rows x 128B, SW128)
// Dead blocks (m0 >= cnt) convert down_proj fp32->fp16 via ticket queue.
#define GU_A      0
#define GU_BG     8192
#define GU_BU     12288
#define GU_STRIDE 16384
#define STAGES    5
#define N_ITERS   32

__global__ __launch_bounds__(256, 2)
void moe_gateup_hmma(const float* __restrict__ gub, const float4* __restrict__ dwn) {
    const int e   = blockIdx.z;
    const int cnt = g_cnt[e];
    const int m0  = blockIdx.x * 128;
    const int tid = threadIdx.x;

    if (m0 >= cnt) {
        // ---- recycled block: convert down_proj chunks ----
        __shared__ int s_c;
        uint2* dst = (uint2*)g_dwn_f16;
        for (;;) {
            if (tid == 0) s_c = atomicAdd(&g_cnt[8], 1);
            __syncthreads();
            int c = s_c;
            __syncthreads();
            if (c >= ND_CHUNKS) return;
            int j = (c * 256 + tid) * 2;
            float4 v0 = dwn[j];
            float4 v1 = dwn[j + 1];
            dst[j]     = make_uint2(pack_f16x2(v0.x, v0.y), pack_f16x2(v0.z, v0.w));
            dst[j + 1] = make_uint2(pack_f16x2(v1.x, v1.y), pack_f16x2(v1.z, v1.w));
        }
    }
    const int n0 = blockIdx.y * 64;

    extern __shared__ char dsm[];
    __shared__ int s_tok[128];
    const uint32_t dbase = (smem_u32(dsm) + 1023u) & ~1023u;

    const int lane = tid & 31, wid = tid >> 5;
    const int mw = wid >> 1, nw = wid & 1;

    if (tid < 128) {
        int gm = m0 + tid;
        s_tok[tid] = (gm < cnt) ? g_tok[e * T_TOK + gm] : g_tok[e * T_TOK];
    }
    __syncthreads();

    const int rA = tid >> 2, pA = tid & 3;       // A: rows rA, rA+64; 16B chunk pA
    const int tA0 = s_tok[rA], tA1 = s_tok[rA + 64];
    const int kB = tid >> 3, pB = tid & 7;       // B: k-row kB; 16B chunk pB
    const size_t gupb = (size_t)e * (H_DIM * I_DIM);      // u32; row stride 1024
    const uint32_t dA0 = swz64(rA * 64 + pA * 16);
    const uint32_t dA1 = swz64((rA + 64) * 64 + pA * 16);
    const uint32_t dB  = swz128(kB * 128 + pB * 16);

#define GU_ISSUE(s_) do { if ((s_) < N_ITERS) {                                              \
    uint32_t bb = dbase + ((s_) % STAGES) * GU_STRIDE;                                       \
    int kh = (s_) * 16;                                                                      \
    CP16(bb + GU_A + dA0, g_x_f16 + (size_t)tA0 * 512 + kh + pA * 4);                        \
    CP16(bb + GU_A + dA1, g_x_f16 + (size_t)tA1 * 512 + kh + pA * 4);                        \
    size_t bro = gupb + (size_t)((s_) * 32 + kB) * 1024 + (n0 >> 1) + pB * 4;                \
    CP16(bb + GU_BG + dB, g_gup_f16 + bro);                                                  \
    CP16(bb + GU_BU + dB, g_gup_f16 + bro + 512);                                            \
} CP_COMMIT(); } while (0)

    float cg[2][4][4], cu[2][4][4];
#pragma unroll
    for (int a = 0; a < 2; a++)
#pragma unroll
        for (int b = 0; b < 4; b++)
#pragma unroll
            for (int c = 0; c < 4; c++) { cg[a][b][c] = 0.f; cu[a][b][c] = 0.f; }

    GU_ISSUE(0);
    GU_ISSUE(1);
    GU_ISSUE(2);

#pragma unroll 1
    for (int it = 0; it < N_ITERS; ++it) {
        GU_ISSUE(it + 3);
        CP_WAIT3();
        __syncthreads();
        uint32_t base = dbase + (it % STAGES) * GU_STRIDE;
#pragma unroll
        for (int s = 0; s < 2; s++) {
            uint32_t am[2][4];
#pragma unroll
            for (int mt = 0; mt < 2; mt++) {
                uint32_t row = mw * 32 + mt * 16 + (lane & 15);
                uint32_t co  = s * 32 + ((lane >> 4) << 4);
                ldsm4(am[mt], base + GU_A + swz64(row * 64 + co));
            }
            uint32_t krow = s * 16 + (lane & 15);
            uint32_t ccol = nw * 64 + ((lane >> 4) << 4);
            uint32_t bg[8], bu[8];
#pragma unroll
            for (int h = 0; h < 2; h++) {
                ldsm4t(bg + 4 * h, base + GU_BG + swz128(krow * 128 + ccol + h * 32));
                ldsm4t(bu + 4 * h, base + GU_BU + swz128(krow * 128 + ccol + h * 32));
            }
#pragma unroll
            for (int mt = 0; mt < 2; mt++)
#pragma unroll
                for (int nf = 0; nf < 4; nf++) {
                    mma16816(cg[mt][nf], am[mt], bg[2*nf], bg[2*nf+1]);
                    mma16816(cu[mt][nf], am[mt], bu[2*nf], bu[2*nf+1]);
                }
        }
        // single sync per iter: safe with 5 stages (write buf (it+3)%5 vs
        // oldest concurrent read buf (it-1)%5 -- distinct mod 5)
    }
#undef GU_ISSUE

    // epilogue: bias + clamped GLU -> g_act (packed fp16)
    const float* gb = gub + e * 2 * I_DIM;
#pragma unroll
    for (int mt = 0; mt < 2; mt++)
#pragma unroll
        for (int r = 0; r < 2; r++) {
            int slot = m0 + mw * 32 + mt * 16 + (lane >> 2) + r * 8;
            if (slot >= cnt) continue;
            size_t abase = ((size_t)(e * T_TOK + slot) * I_DIM) >> 1;
#pragma unroll
            for (int nf = 0; nf < 4; nf++) {
                int col = n0 + nw * 32 + nf * 8 + (lane & 3) * 2;
                float g0 = cg[mt][nf][2 * r]     + gb[col];
                float g1 = cg[mt][nf][2 * r + 1] + gb[col + 1];
                float u0 = cu[mt][nf][2 * r]     + gb[I_DIM + col];
                float u1 = cu[mt][nf][2 * r + 1] + gb[I_DIM + col + 1];
                g0 = fminf(g0, LIMIT); g1 = fminf(g1, LIMIT);
                u0 = fminf(fmaxf(u0, -LIMIT), LIMIT);
                u1 = fminf(fmaxf(u1, -LIMIT), LIMIT);
                float a0 = (u0 + 1.0f) * (g0 / (1.0f + __expf(-ALPHA * g0)));
                float a1 = (u1 + 1.0f) * (g1 / (1.0f + __expf(-ALPHA * g1)));
                g_act_f16[abase + (col >> 1)] = pack_f16x2(a0, a1);
            }
        }
}

// ---------------- kernel 3: down HMMA (fp16, BK=32, 5-stage, depth-3) --------
// Stage (12KB): A 8KB (SW64), B 4KB (SW128)
#define DN_A      0
#define DN_B      8192
#define DN_STRIDE 12288

__global__ __launch_bounds__(256, 2)
void moe_down_hmma(const float* __restrict__ dnb, float* __restrict__ out) {
    const int e   = blockIdx.z;
    const int cnt = g_cnt[e];
    const int m0  = blockIdx.x * 128;
    if (m0 >= cnt) return;
    const int n0  = blockIdx.y * 64;

    extern __shared__ char dsm[];
    const uint32_t dbase = (smem_u32(dsm) + 1023u) & ~1023u;

    const int tid = threadIdx.x, lane = tid & 31, wid = tid >> 5;
    const int mw = wid >> 1, nw = wid & 1;

    const int rA = tid >> 2, pA = tid & 3;
    const int kB = tid >> 3, pB = tid & 7;
    const size_t a0 = (size_t)(e * T_TOK + m0 + rA) * 512;
    const size_t a1 = (size_t)(e * T_TOK + m0 + rA + 64) * 512;
    const size_t dwb = (size_t)e * (I_DIM * H_DIM / 2);
    const uint32_t dA0 = swz64(rA * 64 + pA * 16);
    const uint32_t dA1 = swz64((rA + 64) * 64 + pA * 16);
    const uint32_t dB  = swz128(kB * 128 + pB * 16);

#define DN_ISSUE(s_) do { if ((s_) < N_ITERS) {                                              \
    uint32_t bb = dbase + ((s_) % STAGES) * DN_STRIDE;                                       \
    int kh = (s_) * 16;                                                                      \
    CP16(bb + DN_A + dA0, g_act_f16 + a0 + kh + pA * 4);                                     \
    CP16(bb + DN_A + dA1, g_act_f16 + a1 + kh + pA * 4);                                     \
    size_t bro = dwb + (size_t)((s_) * 32 + kB) * 512 + (n0 >> 1) + pB * 4;                  \
    CP16(bb + DN_B + dB, g_dwn_f16 + bro);                                                   \
} CP_COMMIT(); } while (0)

    float cd[2][4][4];
#pragma unroll
    for (int a = 0; a < 2; a++)
#pragma unroll
        for (int b = 0; b < 4; b++)
#pragma unroll
            for (int c = 0; c < 4; c++) cd[a][b][c] = 0.f;

    DN_ISSUE(0);
    DN_ISSUE(1);
    DN_ISSUE(2);

#pragma unroll 1
    for (int it = 0; it < N_ITERS; ++it) {
        DN_ISSUE(it + 3);
        CP_WAIT3();
        __syncthreads();
        uint32_t base = dbase + (it % STAGES) * DN_STRIDE;
#pragma unroll
        for (int s = 0; s < 2; s++) {
            uint32_t am[2][4];
#pragma unroll
            for (int mt = 0; mt < 2; mt++) {
                uint32_t row = mw * 32 + mt * 16 + (lane & 15);
                uint32_t co  = s * 32 + ((lane >> 4) << 4);
                ldsm4(am[mt], base + DN_A + swz64(row * 64 + co));
            }
            uint32_t krow = s * 16 + (lane & 15);
            uint32_t ccol = nw * 64 + ((lane >> 4) << 4);
            uint32_t bb[8];
#pragma unroll
            for (int h = 0; h < 2; h++)
                ldsm4t(bb + 4 * h, base + DN_B + swz128(krow * 128 + ccol + h * 32));
#pragma unroll
            for (int mt = 0; mt < 2; mt++)
#pragma unroll
                for (int nf = 0; nf < 4; nf++)
                    mma16816(cd[mt][nf], am[mt], bb[2*nf], bb[2*nf+1]);
        }
    }
#undef DN_ISSUE

    const float* db = dnb + e * H_DIM;
#pragma unroll
    for (int mt = 0; mt < 2; mt++)
#pragma unroll
        for (int r = 0; r < 2; r++) {
            int slot = m0 + mw * 32 + mt * 16 + (lane >> 2) + r * 8;
            if (slot >= cnt) continue;
            int   tok = g_tok[e * T_TOK + slot];
            float w   = g_wt [e * T_TOK + slot];
            float* op = out + (size_t)tok * H_DIM;
#pragma unroll
            for (int nf = 0; nf < 4; nf++) {
                int col = n0 + nw * 32 + nf * 8 + (lane & 3) * 2;
                float v0 = (cd[mt][nf][2 * r]     + db[col])     * w;
                float v1 = (cd[mt][nf][2 * r + 1] + db[col + 1]) * w;
                atomicAdd(op + col,     v0);
                atomicAdd(op + col + 1, v1);
            }
        }
}

// ---------------- launch -----------------------------------------------------
extern "C" void kernel_launch(void* const* d_in, const int* in_sizes, int n_in,
                              void* d_out, int out_size) {
    const float* x   = (const float*)d_in[0];
    const float* rw  = (const float*)d_in[1];
    const float* rb  = (const float*)d_in[2];
    const float* gup = (const float*)d_in[3];
    const float* gub = (const float*)d_in[4];
    const float* dwn = (const float*)d_in[5];
    const float* dnb = (const float*)d_in[6];
    float* out = (float*)d_out;

    static bool attr_done = false;
    static void* cnt_addr = nullptr;
    if (!attr_done) {
        cudaFuncSetAttribute(moe_gateup_hmma, cudaFuncAttributeMaxDynamicSharedMemorySize,
                             STAGES * GU_STRIDE + 1024);
        cudaFuncSetAttribute(moe_down_hmma, cudaFuncAttributeMaxDynamicSharedMemorySize,
                             STAGES * DN_STRIDE + 1024);
        cudaGetSymbolAddress(&cnt_addr, g_cnt);
        attr_done = true;
    }

    cudaMemsetAsync(cnt_addr, 0, 16 * sizeof(int));

    prologue_kernel<<<T_TOK + NCV, 256>>>((const float4*)x, (const float4*)gup,
                                          rw, rb, (float4*)out);

    dim3 g1(T_TOK / 128, I_DIM / 64, N_EXP);
    moe_gateup_hmma<<<g1, 256, STAGES * GU_STRIDE + 1024>>>(gub, (const float4*)dwn);

    dim3 g2(T_TOK / 128, H_DIM / 64, N_EXP);
    moe_down_hmma<<<g2, 256, STAGES * DN_STRIDE + 1024>>>(dnb, out);
}